// round 1
// baseline (speedup 1.0000x reference)
#include <cuda_runtime.h>
#include <math.h>

// ---------------------------------------------------------------------------
// Problem constants (fixed by the reference: B=2, N=2048, E=1024, H=16, D=64)
// ---------------------------------------------------------------------------
#define T_TOK   4096          // B*N tokens
#define E_DIM   1024
#define H_NUM   16
#define D_HEAD  64
#define FF_DIM  4096
#define SEQ_N   2048
#define EPS_LN  1e-5f

// ---------------------------------------------------------------------------
// Scratch buffers (allocation-free rule: __device__ globals)
// ---------------------------------------------------------------------------
__device__ float g_h   [(size_t)T_TOK * E_DIM];    // LN output (reused for LN1/LN2)
__device__ float g_qkv [(size_t)T_TOK * 3 * E_DIM];
__device__ float g_attn[(size_t)T_TOK * E_DIM];    // attention output [B,N,E]
__device__ float g_x1  [(size_t)T_TOK * E_DIM];    // x + proj(attn)
__device__ float g_ff  [(size_t)T_TOK * FF_DIM];   // gelu(fc1)

// ---------------------------------------------------------------------------
// Warp reduction helpers
// ---------------------------------------------------------------------------
__device__ __forceinline__ float warp_sum(float v) {
    #pragma unroll
    for (int o = 16; o > 0; o >>= 1) v += __shfl_xor_sync(0xffffffffu, v, o);
    return v;
}
__device__ __forceinline__ float warp_max(float v) {
    #pragma unroll
    for (int o = 16; o > 0; o >>= 1) v = fmaxf(v, __shfl_xor_sync(0xffffffffu, v, o));
    return v;
}

// ---------------------------------------------------------------------------
// LayerNorm: one block per row (E=1024), 256 threads, one float4 per thread
// ---------------------------------------------------------------------------
__global__ void ln_kernel(const float* __restrict__ x,
                          const float* __restrict__ gamma,
                          const float* __restrict__ beta,
                          float* __restrict__ out)
{
    const int row = blockIdx.x;
    const int tid = threadIdx.x;
    const int w   = tid >> 5;
    const int ln  = tid & 31;

    const float4 v = reinterpret_cast<const float4*>(x + (size_t)row * E_DIM)[tid];
    float s  = v.x + v.y + v.z + v.w;
    float sq = v.x * v.x + v.y * v.y + v.z * v.z + v.w * v.w;

    s  = warp_sum(s);
    sq = warp_sum(sq);

    __shared__ float red_s[8], red_q[8];
    __shared__ float s_mu, s_rs;
    if (ln == 0) { red_s[w] = s; red_q[w] = sq; }
    __syncthreads();
    if (w == 0) {
        float ts = (ln < 8) ? red_s[ln] : 0.f;
        float tq = (ln < 8) ? red_q[ln] : 0.f;
        ts = warp_sum(ts);
        tq = warp_sum(tq);
        if (ln == 0) {
            float mu  = ts * (1.0f / E_DIM);
            float var = tq * (1.0f / E_DIM) - mu * mu;
            s_mu = mu;
            s_rs = rsqrtf(var + EPS_LN);
        }
    }
    __syncthreads();
    const float mu = s_mu, rs = s_rs;

    const float4 g = reinterpret_cast<const float4*>(gamma)[tid];
    const float4 b = reinterpret_cast<const float4*>(beta)[tid];
    float4 o;
    o.x = (v.x - mu) * rs * g.x + b.x;
    o.y = (v.y - mu) * rs * g.y + b.y;
    o.z = (v.z - mu) * rs * g.z + b.z;
    o.w = (v.w - mu) * rs * g.w + b.w;
    reinterpret_cast<float4*>(out + (size_t)row * E_DIM)[tid] = o;
}

// ---------------------------------------------------------------------------
// SGEMM: C[M,N] = A[M,K] @ W[K,N] (+ bias, + epilogue)
//   128x128x8 tile, 256 threads, 8x8 register micro-tile.
//   EPI = 0: +bias ; 1: gelu(+bias) ; 2: +bias +res
//   Requires M%128==0, N%128==0, K%8==0 (true for all shapes here).
// ---------------------------------------------------------------------------
template <int EPI>
__global__ void __launch_bounds__(256, 2)
sgemm_kernel(const float* __restrict__ A, const float* __restrict__ W,
             const float* __restrict__ bias, const float* __restrict__ res,
             float* __restrict__ C, int M, int N, int K)
{
    __shared__ float As[8][128];
    __shared__ float Bs[8][128];

    const int tid = threadIdx.x;
    const int tx  = tid & 15;        // 0..15  (N direction)
    const int ty  = tid >> 4;        // 0..15  (M direction)
    const int m0  = blockIdx.y * 128;
    const int n0  = blockIdx.x * 128;

    // A-tile load mapping: 128 rows x 8 cols, one float4 along K per thread
    const int arow = tid >> 1;
    const int acol = (tid & 1) * 4;
    // B-tile load mapping: 8 rows x 128 cols, one float4 along N per thread
    const int brow = tid >> 5;
    const int bcol = (tid & 31) * 4;

    const float* Ap = A + (size_t)(m0 + arow) * K + acol;
    const float* Wp = W + (size_t)brow * N + n0 + bcol;

    float acc[8][8];
    #pragma unroll
    for (int i = 0; i < 8; ++i)
        #pragma unroll
        for (int j = 0; j < 8; ++j) acc[i][j] = 0.f;

    for (int k0 = 0; k0 < K; k0 += 8) {
        const float4 av = *reinterpret_cast<const float4*>(Ap + k0);
        As[acol + 0][arow] = av.x;
        As[acol + 1][arow] = av.y;
        As[acol + 2][arow] = av.z;
        As[acol + 3][arow] = av.w;
        const float4 bv = *reinterpret_cast<const float4*>(Wp + (size_t)k0 * N);
        *reinterpret_cast<float4*>(&Bs[brow][bcol]) = bv;
        __syncthreads();

        #pragma unroll
        for (int k = 0; k < 8; ++k) {
            const float4 a0 = *reinterpret_cast<const float4*>(&As[k][ty * 8]);
            const float4 a1 = *reinterpret_cast<const float4*>(&As[k][ty * 8 + 4]);
            const float4 b0 = *reinterpret_cast<const float4*>(&Bs[k][tx * 8]);
            const float4 b1 = *reinterpret_cast<const float4*>(&Bs[k][tx * 8 + 4]);
            const float a[8] = {a0.x, a0.y, a0.z, a0.w, a1.x, a1.y, a1.z, a1.w};
            const float b[8] = {b0.x, b0.y, b0.z, b0.w, b1.x, b1.y, b1.z, b1.w};
            #pragma unroll
            for (int i = 0; i < 8; ++i)
                #pragma unroll
                for (int j = 0; j < 8; ++j)
                    acc[i][j] = fmaf(a[i], b[j], acc[i][j]);
        }
        __syncthreads();
    }

    // Epilogue
    #pragma unroll
    for (int i = 0; i < 8; ++i) {
        const int row = m0 + ty * 8 + i;
        float* crow = C + (size_t)row * N;
        const float* rrow = (EPI == 2) ? (res + (size_t)row * N) : nullptr;
        #pragma unroll
        for (int j = 0; j < 8; ++j) {
            const int col = n0 + tx * 8 + j;
            float v = acc[i][j] + bias[col];
            if (EPI == 1) {
                v = 0.5f * v * (1.0f + erff(v * 0.70710678118654752f));
            } else if (EPI == 2) {
                v += rrow[col];
            }
            crow[col] = v;
        }
    }
}

// ---------------------------------------------------------------------------
// Flash attention (fp32, online softmax).
//   grid = (SEQ_N/16, B*H), block = 512 threads (16 warps).
//   Each warp owns one query row; block shares 32-key K/V tiles in SMEM.
//   qkv layout: [token][3*E]  with q at h*64, k at E + h*64, v at 2E + h*64.
// ---------------------------------------------------------------------------
#define AQ 16   // query rows per block
#define KT 32   // key tile

__global__ void __launch_bounds__(512, 2)
attn_kernel(const float* __restrict__ qkv, float* __restrict__ out)
{
    __shared__ float Ks[KT][65];
    __shared__ float Vs[KT][65];
    __shared__ float qs[AQ][64];
    __shared__ float ps[AQ][KT];

    const int tid  = threadIdx.x;
    const int w    = tid >> 5;
    const int lane = tid & 31;

    const int bh = blockIdx.y;            // 0..31
    const int b  = bh >> 4;
    const int h  = bh & 15;
    const int qrow = blockIdx.x * AQ + w; // query row within sequence

    const size_t tq = (size_t)b * SEQ_N + qrow;
    const float* qptr = qkv + tq * (3 * E_DIM) + h * D_HEAD;
    // pre-scale q by 1/sqrt(D) = 0.125
    qs[w][lane]      = qptr[lane]      * 0.125f;
    qs[w][lane + 32] = qptr[lane + 32] * 0.125f;

    const float* kbase = qkv + (size_t)b * SEQ_N * (3 * E_DIM) + E_DIM     + h * D_HEAD;
    const float* vbase = qkv + (size_t)b * SEQ_N * (3 * E_DIM) + 2 * E_DIM + h * D_HEAD;

    float m = -1e30f, l = 0.f, a0 = 0.f, a1 = 0.f;

    for (int j0 = 0; j0 < SEQ_N; j0 += KT) {
        __syncthreads();   // prior tile's consumers done before overwrite
        {
            // 32 rows x 64 floats for K and V: 512 float4 each, 512 threads
            const int r = tid >> 4;
            const int c = (tid & 15) << 2;
            const float4 kv = *reinterpret_cast<const float4*>(
                kbase + (size_t)(j0 + r) * (3 * E_DIM) + c);
            Ks[r][c] = kv.x; Ks[r][c + 1] = kv.y; Ks[r][c + 2] = kv.z; Ks[r][c + 3] = kv.w;
            const float4 vv = *reinterpret_cast<const float4*>(
                vbase + (size_t)(j0 + r) * (3 * E_DIM) + c);
            Vs[r][c] = vv.x; Vs[r][c + 1] = vv.y; Vs[r][c + 2] = vv.z; Vs[r][c + 3] = vv.w;
        }
        __syncthreads();

        // score for this lane's key (j0 + lane)
        float s = 0.f;
        #pragma unroll
        for (int d = 0; d < 64; ++d)
            s = fmaf(qs[w][d], Ks[lane][d], s);

        const float mt = warp_max(s);
        const float mn = fmaxf(m, mt);
        const float p  = __expf(s - mn);
        const float alpha = __expf(m - mn);
        l = l * alpha + warp_sum(p);
        m = mn;

        ps[w][lane] = p;
        __syncwarp();

        a0 *= alpha;
        a1 *= alpha;
        #pragma unroll
        for (int j = 0; j < KT; ++j) {
            const float pj = ps[w][j];
            a0 = fmaf(pj, Vs[j][lane],      a0);
            a1 = fmaf(pj, Vs[j][lane + 32], a1);
        }
    }

    const float inv = 1.0f / l;
    float* orow = out + tq * E_DIM + h * D_HEAD;
    orow[lane]      = a0 * inv;
    orow[lane + 32] = a1 * inv;
}

// ---------------------------------------------------------------------------
// Launch
// ---------------------------------------------------------------------------
static float* sym_addr(const void* symbol)
{
    void* p = nullptr;
    cudaGetSymbolAddress(&p, symbol);
    return reinterpret_cast<float*>(p);
}

extern "C" void kernel_launch(void* const* d_in, const int* in_sizes, int n_in,
                              void* d_out, int out_size)
{
    const float* x      = (const float*)d_in[0];
    const float* ln1_g  = (const float*)d_in[1];
    const float* ln1_b  = (const float*)d_in[2];
    const float* qkv_w  = (const float*)d_in[3];
    const float* qkv_b  = (const float*)d_in[4];
    const float* proj_w = (const float*)d_in[5];
    const float* proj_b = (const float*)d_in[6];
    const float* ln2_g  = (const float*)d_in[7];
    const float* ln2_b  = (const float*)d_in[8];
    const float* fc1_w  = (const float*)d_in[9];
    const float* fc1_b  = (const float*)d_in[10];
    const float* fc2_w  = (const float*)d_in[11];
    const float* fc2_b  = (const float*)d_in[12];
    float* out = (float*)d_out;

    float* h    = sym_addr(g_h);
    float* qkv  = sym_addr(g_qkv);
    float* attn = sym_addr(g_attn);
    float* x1   = sym_addr(g_x1);
    float* ff   = sym_addr(g_ff);

    // 1) h = LN1(x)
    ln_kernel<<<T_TOK, 256>>>(x, ln1_g, ln1_b, h);

    // 2) qkv = h @ qkv_w + qkv_b                    [4096 x 3072], K=1024
    sgemm_kernel<0><<<dim3(3 * E_DIM / 128, T_TOK / 128), 256>>>(
        h, qkv_w, qkv_b, nullptr, qkv, T_TOK, 3 * E_DIM, E_DIM);

    // 3) attn = softmax(q k^T / sqrt(D)) v          [4096 x 1024]
    attn_kernel<<<dim3(SEQ_N / AQ, 2 * H_NUM), 512>>>(qkv, attn);

    // 4) x1 = x + attn @ proj_w + proj_b            [4096 x 1024], K=1024
    sgemm_kernel<2><<<dim3(E_DIM / 128, T_TOK / 128), 256>>>(
        attn, proj_w, proj_b, x, x1, T_TOK, E_DIM, E_DIM);

    // 5) h = LN2(x1)
    ln_kernel<<<T_TOK, 256>>>(x1, ln2_g, ln2_b, h);

    // 6) ff = gelu(h @ fc1_w + fc1_b)               [4096 x 4096], K=1024
    sgemm_kernel<1><<<dim3(FF_DIM / 128, T_TOK / 128), 256>>>(
        h, fc1_w, fc1_b, nullptr, ff, T_TOK, FF_DIM, E_DIM);

    // 7) out = x1 + ff @ fc2_w + fc2_b              [4096 x 1024], K=4096
    sgemm_kernel<2><<<dim3(E_DIM / 128, T_TOK / 128), 256>>>(
        ff, fc2_w, fc2_b, x1, out, T_TOK, E_DIM, FF_DIM);
}

// round 2
// speedup vs baseline: 1.2446x; 1.2446x over previous
#include <cuda_runtime.h>
#include <cuda_bf16.h>
#include <mma.h>
#include <math.h>

using namespace nvcuda;

// ---------------------------------------------------------------------------
// Problem constants (B=2, N=2048, E=1024, H=16, D=64, FF=4096)
// ---------------------------------------------------------------------------
#define T_TOK   4096
#define E_DIM   1024
#define H_NUM   16
#define D_HEAD  64
#define FF_DIM  4096
#define SEQ_N   2048
#define EPS_LN  1e-5f

// ---------------------------------------------------------------------------
// Scratch (__device__ globals; allocation-free rule)
// ---------------------------------------------------------------------------
__device__ __nv_bfloat16 g_ahi[(size_t)T_TOK * FF_DIM];   // activation split (reused)
__device__ __nv_bfloat16 g_alo[(size_t)T_TOK * FF_DIM];
__device__ __nv_bfloat16 g_whi[(size_t)E_DIM * FF_DIM];   // weight split (reused)
__device__ __nv_bfloat16 g_wlo[(size_t)E_DIM * FF_DIM];
__device__ float g_craw[(size_t)T_TOK * FF_DIM];          // raw GEMM out (reused)
__device__ float g_qkv [(size_t)T_TOK * 3 * E_DIM];
__device__ float g_attn[(size_t)T_TOK * E_DIM];
__device__ float g_x1  [(size_t)T_TOK * E_DIM];

// ---------------------------------------------------------------------------
// Warp reductions
// ---------------------------------------------------------------------------
__device__ __forceinline__ float warp_sum(float v) {
    #pragma unroll
    for (int o = 16; o > 0; o >>= 1) v += __shfl_xor_sync(0xffffffffu, v, o);
    return v;
}
__device__ __forceinline__ float warp_max(float v) {
    #pragma unroll
    for (int o = 16; o > 0; o >>= 1) v = fmaxf(v, __shfl_xor_sync(0xffffffffu, v, o));
    return v;
}

__device__ __forceinline__ void split_write(float f, __nv_bfloat16& hi, __nv_bfloat16& lo) {
    __nv_bfloat16 h = __float2bfloat16(f);
    hi = h;
    lo = __float2bfloat16(f - __bfloat162float(h));
}

// ---------------------------------------------------------------------------
// LayerNorm -> hi/lo bf16 split (one block per row, 256 threads, float4 each)
// ---------------------------------------------------------------------------
__global__ void ln_split_kernel(const float* __restrict__ x,
                                const float* __restrict__ gamma,
                                const float* __restrict__ beta,
                                __nv_bfloat16* __restrict__ ohi,
                                __nv_bfloat16* __restrict__ olo)
{
    const int row = blockIdx.x;
    const int tid = threadIdx.x;
    const int w   = tid >> 5;
    const int ln  = tid & 31;

    const float4 v = reinterpret_cast<const float4*>(x + (size_t)row * E_DIM)[tid];
    float s  = v.x + v.y + v.z + v.w;
    float sq = v.x * v.x + v.y * v.y + v.z * v.z + v.w * v.w;
    s  = warp_sum(s);
    sq = warp_sum(sq);

    __shared__ float red_s[8], red_q[8];
    __shared__ float s_mu, s_rs;
    if (ln == 0) { red_s[w] = s; red_q[w] = sq; }
    __syncthreads();
    if (w == 0) {
        float ts = (ln < 8) ? red_s[ln] : 0.f;
        float tq = (ln < 8) ? red_q[ln] : 0.f;
        ts = warp_sum(ts); tq = warp_sum(tq);
        if (ln == 0) {
            float mu  = ts * (1.0f / E_DIM);
            float var = tq * (1.0f / E_DIM) - mu * mu;
            s_mu = mu; s_rs = rsqrtf(var + EPS_LN);
        }
    }
    __syncthreads();
    const float mu = s_mu, rs = s_rs;

    const float4 g = reinterpret_cast<const float4*>(gamma)[tid];
    const float4 b = reinterpret_cast<const float4*>(beta)[tid];
    float o[4];
    o[0] = (v.x - mu) * rs * g.x + b.x;
    o[1] = (v.y - mu) * rs * g.y + b.y;
    o[2] = (v.z - mu) * rs * g.z + b.z;
    o[3] = (v.w - mu) * rs * g.w + b.w;

    __nv_bfloat16 h4[4], l4[4];
    #pragma unroll
    for (int j = 0; j < 4; ++j) split_write(o[j], h4[j], l4[j]);
    const size_t off = (size_t)row * E_DIM + tid * 4;
    *reinterpret_cast<uint2*>(ohi + off) = *reinterpret_cast<uint2*>(h4);
    *reinterpret_cast<uint2*>(olo + off) = *reinterpret_cast<uint2*>(l4);
}

// ---------------------------------------------------------------------------
// fp32 -> hi/lo bf16 split (elementwise, 4 per thread)
// ---------------------------------------------------------------------------
__global__ void split_kernel(const float* __restrict__ src,
                             __nv_bfloat16* __restrict__ hi,
                             __nv_bfloat16* __restrict__ lo, int n)
{
    const int i = (blockIdx.x * blockDim.x + threadIdx.x) * 4;
    if (i >= n) return;
    const float4 v = *reinterpret_cast<const float4*>(src + i);
    const float f[4] = {v.x, v.y, v.z, v.w};
    __nv_bfloat16 h4[4], l4[4];
    #pragma unroll
    for (int j = 0; j < 4; ++j) split_write(f[j], h4[j], l4[j]);
    *reinterpret_cast<uint2*>(hi + i) = *reinterpret_cast<uint2*>(h4);
    *reinterpret_cast<uint2*>(lo + i) = *reinterpret_cast<uint2*>(l4);
}

// ---------------------------------------------------------------------------
// bf16 split GEMM (tensor cores via wmma m16n16k16).
// C[M,N] = (Ahi+Alo)[M,K] @ (Whi+Wlo)[K,N]  using 3-term compensation.
// Block 128x128, 8 warps (warp tile 64x32), k-tile 32, reg-prefetch pipeline.
// ---------------------------------------------------------------------------
__global__ void __launch_bounds__(256)
gemm_bf16_split(const __nv_bfloat16* __restrict__ Ahi, const __nv_bfloat16* __restrict__ Alo,
                const __nv_bfloat16* __restrict__ Bhi, const __nv_bfloat16* __restrict__ Blo,
                float* __restrict__ C, int M, int N, int K)
{
    __shared__ __nv_bfloat16 As[2][128][40];   // [hi/lo][row][k] padded
    __shared__ __nv_bfloat16 Bs[2][32][136];   // [hi/lo][k][n]  padded

    const int tid = threadIdx.x;
    const int wid = tid >> 5;
    const int wm  = wid & 1;     // 2 warps in M
    const int wn  = wid >> 1;    // 4 warps in N
    const int m0  = blockIdx.y * 128;
    const int n0  = blockIdx.x * 128;

    // A chunks: 128 rows x 4 chunks(16B); c = tid*2 + r
    // B chunks: 32 rows x 16 chunks;      c = tid*2 + r
    wmma::fragment<wmma::accumulator, 16, 16, 16, float> acc[4][2];
    #pragma unroll
    for (int i = 0; i < 4; ++i)
        #pragma unroll
        for (int j = 0; j < 2; ++j) wmma::fill_fragment(acc[i][j], 0.0f);

    int4 pa[2][2], pb[2][2];

    // prologue load of k0 = 0
    #pragma unroll
    for (int h = 0; h < 2; ++h) {
        const __nv_bfloat16* Asrc = h ? Alo : Ahi;
        const __nv_bfloat16* Bsrc = h ? Blo : Bhi;
        #pragma unroll
        for (int r = 0; r < 2; ++r) {
            const int ca = tid * 2 + r;
            pa[h][r] = *reinterpret_cast<const int4*>(
                Asrc + (size_t)(m0 + (ca >> 2)) * K + (ca & 3) * 8);
            pb[h][r] = *reinterpret_cast<const int4*>(
                Bsrc + (size_t)(ca >> 4) * N + n0 + (ca & 15) * 8);
        }
    }

    for (int k0 = 0; k0 < K; k0 += 32) {
        // store staged regs to smem
        #pragma unroll
        for (int h = 0; h < 2; ++h) {
            #pragma unroll
            for (int r = 0; r < 2; ++r) {
                const int ca = tid * 2 + r;
                *reinterpret_cast<int4*>(&As[h][ca >> 2][(ca & 3) * 8]) = pa[h][r];
                *reinterpret_cast<int4*>(&Bs[h][ca >> 4][(ca & 15) * 8]) = pb[h][r];
            }
        }
        __syncthreads();

        // prefetch next k-tile while computing
        if (k0 + 32 < K) {
            #pragma unroll
            for (int h = 0; h < 2; ++h) {
                const __nv_bfloat16* Asrc = h ? Alo : Ahi;
                const __nv_bfloat16* Bsrc = h ? Blo : Bhi;
                #pragma unroll
                for (int r = 0; r < 2; ++r) {
                    const int ca = tid * 2 + r;
                    pa[h][r] = *reinterpret_cast<const int4*>(
                        Asrc + (size_t)(m0 + (ca >> 2)) * K + k0 + 32 + (ca & 3) * 8);
                    pb[h][r] = *reinterpret_cast<const int4*>(
                        Bsrc + (size_t)(k0 + 32 + (ca >> 4)) * N + n0 + (ca & 15) * 8);
                }
            }
        }

        #pragma unroll
        for (int kk = 0; kk < 2; ++kk) {
            wmma::fragment<wmma::matrix_a, 16, 16, 16, __nv_bfloat16, wmma::row_major> ah[4], al[4];
            wmma::fragment<wmma::matrix_b, 16, 16, 16, __nv_bfloat16, wmma::row_major> bh[2], bl[2];
            #pragma unroll
            for (int i = 0; i < 4; ++i) {
                wmma::load_matrix_sync(ah[i], &As[0][wm * 64 + i * 16][kk * 16], 40);
                wmma::load_matrix_sync(al[i], &As[1][wm * 64 + i * 16][kk * 16], 40);
            }
            #pragma unroll
            for (int j = 0; j < 2; ++j) {
                wmma::load_matrix_sync(bh[j], &Bs[0][kk * 16][wn * 32 + j * 16], 136);
                wmma::load_matrix_sync(bl[j], &Bs[1][kk * 16][wn * 32 + j * 16], 136);
            }
            #pragma unroll
            for (int i = 0; i < 4; ++i)
                #pragma unroll
                for (int j = 0; j < 2; ++j) {
                    wmma::mma_sync(acc[i][j], ah[i], bh[j], acc[i][j]);
                    wmma::mma_sync(acc[i][j], ah[i], bl[j], acc[i][j]);
                    wmma::mma_sync(acc[i][j], al[i], bh[j], acc[i][j]);
                }
        }
        __syncthreads();
    }

    #pragma unroll
    for (int i = 0; i < 4; ++i)
        #pragma unroll
        for (int j = 0; j < 2; ++j)
            wmma::store_matrix_sync(&C[(size_t)(m0 + wm * 64 + i * 16) * N + n0 + wn * 32 + j * 16],
                                    acc[i][j], N, wmma::mem_row_major);
}

// ---------------------------------------------------------------------------
// Epilogues (elementwise over [total], col = idx % N), 4 elems/thread
// ---------------------------------------------------------------------------
__global__ void epi_bias(const float* __restrict__ C, const float* __restrict__ bias,
                         float* __restrict__ out, int N, int total)
{
    const int i = (blockIdx.x * blockDim.x + threadIdx.x) * 4;
    if (i >= total) return;
    const int col = i & (N - 1);
    const float4 c = *reinterpret_cast<const float4*>(C + i);
    const float4 b = *reinterpret_cast<const float4*>(bias + col);
    float4 o = {c.x + b.x, c.y + b.y, c.z + b.z, c.w + b.w};
    *reinterpret_cast<float4*>(out + i) = o;
}

__global__ void epi_bias_res(const float* __restrict__ C, const float* __restrict__ bias,
                             const float* __restrict__ res, float* __restrict__ out,
                             int N, int total)
{
    const int i = (blockIdx.x * blockDim.x + threadIdx.x) * 4;
    if (i >= total) return;
    const int col = i & (N - 1);
    const float4 c = *reinterpret_cast<const float4*>(C + i);
    const float4 b = *reinterpret_cast<const float4*>(bias + col);
    const float4 r = *reinterpret_cast<const float4*>(res + i);
    float4 o = {c.x + b.x + r.x, c.y + b.y + r.y, c.z + b.z + r.z, c.w + b.w + r.w};
    *reinterpret_cast<float4*>(out + i) = o;
}

__global__ void epi_gelu_split(const float* __restrict__ C, const float* __restrict__ bias,
                               __nv_bfloat16* __restrict__ hi, __nv_bfloat16* __restrict__ lo,
                               int N, int total)
{
    const int i = (blockIdx.x * blockDim.x + threadIdx.x) * 4;
    if (i >= total) return;
    const int col = i & (N - 1);
    const float4 c = *reinterpret_cast<const float4*>(C + i);
    const float4 b = *reinterpret_cast<const float4*>(bias + col);
    float f[4] = {c.x + b.x, c.y + b.y, c.z + b.z, c.w + b.w};
    __nv_bfloat16 h4[4], l4[4];
    #pragma unroll
    for (int j = 0; j < 4; ++j) {
        const float g = 0.5f * f[j] * (1.0f + erff(f[j] * 0.70710678118654752f));
        split_write(g, h4[j], l4[j]);
    }
    *reinterpret_cast<uint2*>(hi + i) = *reinterpret_cast<uint2*>(h4);
    *reinterpret_cast<uint2*>(lo + i) = *reinterpret_cast<uint2*>(l4);
}

// ---------------------------------------------------------------------------
// Flash attention (fp32, online softmax). float4 smem reads, stride-68 rows
// (lane*68 mod 32 == 4*lane -> conflict-free 16B phases).
// ---------------------------------------------------------------------------
#define AQ 16
#define KT 32

__global__ void __launch_bounds__(512, 2)
attn_kernel(const float* __restrict__ qkv, float* __restrict__ out)
{
    __shared__ float Ks[KT][68];
    __shared__ float Vs[KT][68];
    __shared__ float qs[AQ][64];
    __shared__ float ps[AQ][KT];

    const int tid  = threadIdx.x;
    const int w    = tid >> 5;
    const int lane = tid & 31;

    const int bh = blockIdx.y;
    const int b  = bh >> 4;
    const int h  = bh & 15;
    const int qrow = blockIdx.x * AQ + w;

    const size_t tq = (size_t)b * SEQ_N + qrow;
    const float* qptr = qkv + tq * (3 * E_DIM) + h * D_HEAD;
    qs[w][lane]      = qptr[lane]      * 0.125f;
    qs[w][lane + 32] = qptr[lane + 32] * 0.125f;

    const float* kbase = qkv + (size_t)b * SEQ_N * (3 * E_DIM) + E_DIM     + h * D_HEAD;
    const float* vbase = qkv + (size_t)b * SEQ_N * (3 * E_DIM) + 2 * E_DIM + h * D_HEAD;

    float m = -1e30f, l = 0.f, a0 = 0.f, a1 = 0.f;

    for (int j0 = 0; j0 < SEQ_N; j0 += KT) {
        __syncthreads();
        {
            const int r = tid >> 4;
            const int c = (tid & 15) << 2;
            const float4 kv = *reinterpret_cast<const float4*>(
                kbase + (size_t)(j0 + r) * (3 * E_DIM) + c);
            *reinterpret_cast<float4*>(&Ks[r][c]) = kv;
            const float4 vv = *reinterpret_cast<const float4*>(
                vbase + (size_t)(j0 + r) * (3 * E_DIM) + c);
            *reinterpret_cast<float4*>(&Vs[r][c]) = vv;
        }
        __syncthreads();

        float s = 0.f;
        #pragma unroll
        for (int d4 = 0; d4 < 16; ++d4) {
            const float4 kq = *reinterpret_cast<const float4*>(&Ks[lane][d4 * 4]);
            const float4 qq = *reinterpret_cast<const float4*>(&qs[w][d4 * 4]);
            s = fmaf(kq.x, qq.x, s);
            s = fmaf(kq.y, qq.y, s);
            s = fmaf(kq.z, qq.z, s);
            s = fmaf(kq.w, qq.w, s);
        }

        const float mt = warp_max(s);
        const float mn = fmaxf(m, mt);
        const float p  = __expf(s - mn);
        const float alpha = __expf(m - mn);
        l = l * alpha + warp_sum(p);
        m = mn;

        ps[w][lane] = p;
        __syncwarp();

        a0 *= alpha;
        a1 *= alpha;
        #pragma unroll
        for (int j4 = 0; j4 < 8; ++j4) {
            const float4 p4 = *reinterpret_cast<const float4*>(&ps[w][j4 * 4]);
            a0 = fmaf(p4.x, Vs[j4 * 4 + 0][lane], a0);
            a1 = fmaf(p4.x, Vs[j4 * 4 + 0][lane + 32], a1);
            a0 = fmaf(p4.y, Vs[j4 * 4 + 1][lane], a0);
            a1 = fmaf(p4.y, Vs[j4 * 4 + 1][lane + 32], a1);
            a0 = fmaf(p4.z, Vs[j4 * 4 + 2][lane], a0);
            a1 = fmaf(p4.z, Vs[j4 * 4 + 2][lane + 32], a1);
            a0 = fmaf(p4.w, Vs[j4 * 4 + 3][lane], a0);
            a1 = fmaf(p4.w, Vs[j4 * 4 + 3][lane + 32], a1);
        }
    }

    const float inv = 1.0f / l;
    float* orow = out + tq * E_DIM + h * D_HEAD;
    orow[lane]      = a0 * inv;
    orow[lane + 32] = a1 * inv;
}

// ---------------------------------------------------------------------------
// Launch
// ---------------------------------------------------------------------------
static float* sym_addr_f(const void* symbol)
{
    void* p = nullptr;
    cudaGetSymbolAddress(&p, symbol);
    return reinterpret_cast<float*>(p);
}
static __nv_bfloat16* sym_addr_b(const void* symbol)
{
    void* p = nullptr;
    cudaGetSymbolAddress(&p, symbol);
    return reinterpret_cast<__nv_bfloat16*>(p);
}

extern "C" void kernel_launch(void* const* d_in, const int* in_sizes, int n_in,
                              void* d_out, int out_size)
{
    const float* x      = (const float*)d_in[0];
    const float* ln1_g  = (const float*)d_in[1];
    const float* ln1_b  = (const float*)d_in[2];
    const float* qkv_w  = (const float*)d_in[3];
    const float* qkv_b  = (const float*)d_in[4];
    const float* proj_w = (const float*)d_in[5];
    const float* proj_b = (const float*)d_in[6];
    const float* ln2_g  = (const float*)d_in[7];
    const float* ln2_b  = (const float*)d_in[8];
    const float* fc1_w  = (const float*)d_in[9];
    const float* fc1_b  = (const float*)d_in[10];
    const float* fc2_w  = (const float*)d_in[11];
    const float* fc2_b  = (const float*)d_in[12];
    float* out = (float*)d_out;

    __nv_bfloat16* ahi = sym_addr_b(g_ahi);
    __nv_bfloat16* alo = sym_addr_b(g_alo);
    __nv_bfloat16* whi = sym_addr_b(g_whi);
    __nv_bfloat16* wlo = sym_addr_b(g_wlo);
    float* craw = sym_addr_f(g_craw);
    float* qkv  = sym_addr_f(g_qkv);
    float* attn = sym_addr_f(g_attn);
    float* x1   = sym_addr_f(g_x1);

    const int n_qkvw = E_DIM * 3 * E_DIM;       // 3.1M
    const int n_projw = E_DIM * E_DIM;          // 1M
    const int n_fc1w = E_DIM * FF_DIM;          // 4.2M
    const int n_fc2w = FF_DIM * E_DIM;          // 4.2M

    // ---- 1) h = LN1(x) -> split
    ln_split_kernel<<<T_TOK, 256>>>(x, ln1_g, ln1_b, ahi, alo);

    // ---- 2) qkv = h @ qkv_w + qkv_b
    split_kernel<<<n_qkvw / 1024, 256>>>(qkv_w, whi, wlo, n_qkvw);
    gemm_bf16_split<<<dim3(3 * E_DIM / 128, T_TOK / 128), 256>>>(
        ahi, alo, whi, wlo, craw, T_TOK, 3 * E_DIM, E_DIM);
    epi_bias<<<(T_TOK * 3 * E_DIM) / 1024, 256>>>(craw, qkv_b, qkv, 3 * E_DIM, T_TOK * 3 * E_DIM);

    // ---- 3) attention
    attn_kernel<<<dim3(SEQ_N / AQ, 2 * H_NUM), 512>>>(qkv, attn);

    // ---- 4) x1 = x + attn @ proj_w + proj_b
    split_kernel<<<(T_TOK * E_DIM) / 1024, 256>>>(attn, ahi, alo, T_TOK * E_DIM);
    split_kernel<<<n_projw / 1024, 256>>>(proj_w, whi, wlo, n_projw);
    gemm_bf16_split<<<dim3(E_DIM / 128, T_TOK / 128), 256>>>(
        ahi, alo, whi, wlo, craw, T_TOK, E_DIM, E_DIM);
    epi_bias_res<<<(T_TOK * E_DIM) / 1024, 256>>>(craw, proj_b, x, x1, E_DIM, T_TOK * E_DIM);

    // ---- 5) h = LN2(x1) -> split
    ln_split_kernel<<<T_TOK, 256>>>(x1, ln2_g, ln2_b, ahi, alo);

    // ---- 6) ff = gelu(h @ fc1_w + fc1_b) -> split
    split_kernel<<<n_fc1w / 1024, 256>>>(fc1_w, whi, wlo, n_fc1w);
    gemm_bf16_split<<<dim3(FF_DIM / 128, T_TOK / 128), 256>>>(
        ahi, alo, whi, wlo, craw, T_TOK, FF_DIM, E_DIM);
    epi_gelu_split<<<(T_TOK * FF_DIM) / 1024, 256>>>(craw, fc1_b, ahi, alo, FF_DIM, T_TOK * FF_DIM);

    // ---- 7) out = x1 + ff @ fc2_w + fc2_b
    split_kernel<<<n_fc2w / 1024, 256>>>(fc2_w, whi, wlo, n_fc2w);
    gemm_bf16_split<<<dim3(E_DIM / 128, T_TOK / 128), 256>>>(
        ahi, alo, whi, wlo, craw, T_TOK, E_DIM, FF_DIM);
    epi_bias_res<<<(T_TOK * E_DIM) / 1024, 256>>>(craw, fc2_b, x1, out, E_DIM, T_TOK * E_DIM);
}

// round 3
// speedup vs baseline: 2.3960x; 1.9251x over previous
#include <cuda_runtime.h>
#include <cuda_bf16.h>
#include <mma.h>
#include <math.h>

using namespace nvcuda;

// ---------------------------------------------------------------------------
// Problem constants (B=2, N=2048, E=1024, H=16, D=64, FF=4096)
// ---------------------------------------------------------------------------
#define T_TOK   4096
#define E_DIM   1024
#define H_NUM   16
#define D_HEAD  64
#define FF_DIM  4096
#define SEQ_N   2048
#define EPS_LN  1e-5f

// ---------------------------------------------------------------------------
// Scratch (__device__ globals; allocation-free rule)
// ---------------------------------------------------------------------------
__device__ __nv_bfloat16 g_ahi[(size_t)T_TOK * FF_DIM];
__device__ __nv_bfloat16 g_alo[(size_t)T_TOK * FF_DIM];
__device__ __nv_bfloat16 g_whi[(size_t)E_DIM * FF_DIM];
__device__ __nv_bfloat16 g_wlo[(size_t)E_DIM * FF_DIM];
__device__ float g_craw[(size_t)T_TOK * FF_DIM];
__device__ float g_x1  [(size_t)T_TOK * E_DIM];
// attention operand splits, head-major: [B*H][N][64]
__device__ __nv_bfloat16 g_qhi[(size_t)T_TOK * E_DIM];
__device__ __nv_bfloat16 g_qlo[(size_t)T_TOK * E_DIM];
__device__ __nv_bfloat16 g_khi[(size_t)T_TOK * E_DIM];
__device__ __nv_bfloat16 g_klo[(size_t)T_TOK * E_DIM];
__device__ __nv_bfloat16 g_vhi[(size_t)T_TOK * E_DIM];
__device__ __nv_bfloat16 g_vlo[(size_t)T_TOK * E_DIM];

// ---------------------------------------------------------------------------
// Helpers
// ---------------------------------------------------------------------------
__device__ __forceinline__ float warp_sum(float v) {
    #pragma unroll
    for (int o = 16; o > 0; o >>= 1) v += __shfl_xor_sync(0xffffffffu, v, o);
    return v;
}

__device__ __forceinline__ void split_write(float f, __nv_bfloat16& hi, __nv_bfloat16& lo) {
    __nv_bfloat16 h = __float2bfloat16(f);
    hi = h;
    lo = __float2bfloat16(f - __bfloat162float(h));
}

// ---------------------------------------------------------------------------
// LayerNorm -> hi/lo bf16 split
// ---------------------------------------------------------------------------
__global__ void ln_split_kernel(const float* __restrict__ x,
                                const float* __restrict__ gamma,
                                const float* __restrict__ beta,
                                __nv_bfloat16* __restrict__ ohi,
                                __nv_bfloat16* __restrict__ olo)
{
    const int row = blockIdx.x;
    const int tid = threadIdx.x;
    const int w   = tid >> 5;
    const int ln  = tid & 31;

    const float4 v = reinterpret_cast<const float4*>(x + (size_t)row * E_DIM)[tid];
    float s  = v.x + v.y + v.z + v.w;
    float sq = v.x * v.x + v.y * v.y + v.z * v.z + v.w * v.w;
    s  = warp_sum(s);
    sq = warp_sum(sq);

    __shared__ float red_s[8], red_q[8];
    __shared__ float s_mu, s_rs;
    if (ln == 0) { red_s[w] = s; red_q[w] = sq; }
    __syncthreads();
    if (w == 0) {
        float ts = (ln < 8) ? red_s[ln] : 0.f;
        float tq = (ln < 8) ? red_q[ln] : 0.f;
        ts = warp_sum(ts); tq = warp_sum(tq);
        if (ln == 0) {
            float mu  = ts * (1.0f / E_DIM);
            float var = tq * (1.0f / E_DIM) - mu * mu;
            s_mu = mu; s_rs = rsqrtf(var + EPS_LN);
        }
    }
    __syncthreads();
    const float mu = s_mu, rs = s_rs;

    const float4 g = reinterpret_cast<const float4*>(gamma)[tid];
    const float4 b = reinterpret_cast<const float4*>(beta)[tid];
    float o[4];
    o[0] = (v.x - mu) * rs * g.x + b.x;
    o[1] = (v.y - mu) * rs * g.y + b.y;
    o[2] = (v.z - mu) * rs * g.z + b.z;
    o[3] = (v.w - mu) * rs * g.w + b.w;

    __nv_bfloat16 h4[4], l4[4];
    #pragma unroll
    for (int j = 0; j < 4; ++j) split_write(o[j], h4[j], l4[j]);
    const size_t off = (size_t)row * E_DIM + tid * 4;
    *reinterpret_cast<uint2*>(ohi + off) = *reinterpret_cast<uint2*>(h4);
    *reinterpret_cast<uint2*>(olo + off) = *reinterpret_cast<uint2*>(l4);
}

// ---------------------------------------------------------------------------
// fp32 -> hi/lo split (weights)
// ---------------------------------------------------------------------------
__global__ void split_kernel(const float* __restrict__ src,
                             __nv_bfloat16* __restrict__ hi,
                             __nv_bfloat16* __restrict__ lo, int n)
{
    const int i = (blockIdx.x * blockDim.x + threadIdx.x) * 4;
    if (i >= n) return;
    const float4 v = *reinterpret_cast<const float4*>(src + i);
    const float f[4] = {v.x, v.y, v.z, v.w};
    __nv_bfloat16 h4[4], l4[4];
    #pragma unroll
    for (int j = 0; j < 4; ++j) split_write(f[j], h4[j], l4[j]);
    *reinterpret_cast<uint2*>(hi + i) = *reinterpret_cast<uint2*>(h4);
    *reinterpret_cast<uint2*>(lo + i) = *reinterpret_cast<uint2*>(l4);
}

// ---------------------------------------------------------------------------
// bf16 split GEMM (wmma m16n16k16, 3-term). 128x128 block, 8 warps, k-tile 32.
// ---------------------------------------------------------------------------
__global__ void __launch_bounds__(256)
gemm_bf16_split(const __nv_bfloat16* __restrict__ Ahi, const __nv_bfloat16* __restrict__ Alo,
                const __nv_bfloat16* __restrict__ Bhi, const __nv_bfloat16* __restrict__ Blo,
                float* __restrict__ C, int M, int N, int K)
{
    __shared__ __nv_bfloat16 As[2][128][40];
    __shared__ __nv_bfloat16 Bs[2][32][136];

    const int tid = threadIdx.x;
    const int wid = tid >> 5;
    const int wm  = wid & 1;
    const int wn  = wid >> 1;
    const int m0  = blockIdx.y * 128;
    const int n0  = blockIdx.x * 128;

    wmma::fragment<wmma::accumulator, 16, 16, 16, float> acc[4][2];
    #pragma unroll
    for (int i = 0; i < 4; ++i)
        #pragma unroll
        for (int j = 0; j < 2; ++j) wmma::fill_fragment(acc[i][j], 0.0f);

    int4 pa[2][2], pb[2][2];

    #pragma unroll
    for (int h = 0; h < 2; ++h) {
        const __nv_bfloat16* Asrc = h ? Alo : Ahi;
        const __nv_bfloat16* Bsrc = h ? Blo : Bhi;
        #pragma unroll
        for (int r = 0; r < 2; ++r) {
            const int ca = tid * 2 + r;
            pa[h][r] = *reinterpret_cast<const int4*>(
                Asrc + (size_t)(m0 + (ca >> 2)) * K + (ca & 3) * 8);
            pb[h][r] = *reinterpret_cast<const int4*>(
                Bsrc + (size_t)(ca >> 4) * N + n0 + (ca & 15) * 8);
        }
    }

    for (int k0 = 0; k0 < K; k0 += 32) {
        #pragma unroll
        for (int h = 0; h < 2; ++h) {
            #pragma unroll
            for (int r = 0; r < 2; ++r) {
                const int ca = tid * 2 + r;
                *reinterpret_cast<int4*>(&As[h][ca >> 2][(ca & 3) * 8]) = pa[h][r];
                *reinterpret_cast<int4*>(&Bs[h][ca >> 4][(ca & 15) * 8]) = pb[h][r];
            }
        }
        __syncthreads();

        if (k0 + 32 < K) {
            #pragma unroll
            for (int h = 0; h < 2; ++h) {
                const __nv_bfloat16* Asrc = h ? Alo : Ahi;
                const __nv_bfloat16* Bsrc = h ? Blo : Bhi;
                #pragma unroll
                for (int r = 0; r < 2; ++r) {
                    const int ca = tid * 2 + r;
                    pa[h][r] = *reinterpret_cast<const int4*>(
                        Asrc + (size_t)(m0 + (ca >> 2)) * K + k0 + 32 + (ca & 3) * 8);
                    pb[h][r] = *reinterpret_cast<const int4*>(
                        Bsrc + (size_t)(k0 + 32 + (ca >> 4)) * N + n0 + (ca & 15) * 8);
                }
            }
        }

        #pragma unroll
        for (int kk = 0; kk < 2; ++kk) {
            wmma::fragment<wmma::matrix_a, 16, 16, 16, __nv_bfloat16, wmma::row_major> ah[4], al[4];
            wmma::fragment<wmma::matrix_b, 16, 16, 16, __nv_bfloat16, wmma::row_major> bh[2], bl[2];
            #pragma unroll
            for (int i = 0; i < 4; ++i) {
                wmma::load_matrix_sync(ah[i], &As[0][wm * 64 + i * 16][kk * 16], 40);
                wmma::load_matrix_sync(al[i], &As[1][wm * 64 + i * 16][kk * 16], 40);
            }
            #pragma unroll
            for (int j = 0; j < 2; ++j) {
                wmma::load_matrix_sync(bh[j], &Bs[0][kk * 16][wn * 32 + j * 16], 136);
                wmma::load_matrix_sync(bl[j], &Bs[1][kk * 16][wn * 32 + j * 16], 136);
            }
            #pragma unroll
            for (int i = 0; i < 4; ++i)
                #pragma unroll
                for (int j = 0; j < 2; ++j) {
                    wmma::mma_sync(acc[i][j], ah[i], bh[j], acc[i][j]);
                    wmma::mma_sync(acc[i][j], ah[i], bl[j], acc[i][j]);
                    wmma::mma_sync(acc[i][j], al[i], bh[j], acc[i][j]);
                }
        }
        __syncthreads();
    }

    #pragma unroll
    for (int i = 0; i < 4; ++i)
        #pragma unroll
        for (int j = 0; j < 2; ++j)
            wmma::store_matrix_sync(&C[(size_t)(m0 + wm * 64 + i * 16) * N + n0 + wn * 32 + j * 16],
                                    acc[i][j], N, wmma::mem_row_major);
}

// ---------------------------------------------------------------------------
// QKV epilogue: craw + bias -> head-major bf16 hi/lo splits (q scaled 0.125)
// ---------------------------------------------------------------------------
__global__ void epi_qkv_split(const float* __restrict__ C, const float* __restrict__ bias,
                              __nv_bfloat16* __restrict__ qhi, __nv_bfloat16* __restrict__ qlo,
                              __nv_bfloat16* __restrict__ khi, __nv_bfloat16* __restrict__ klo,
                              __nv_bfloat16* __restrict__ vhi, __nv_bfloat16* __restrict__ vlo)
{
    const size_t i = ((size_t)blockIdx.x * blockDim.x + threadIdx.x) * 8;
    const int t = (int)(i / (3 * E_DIM));
    const int c = (int)(i % (3 * E_DIM));

    float f[8];
    {
        const float4 a = *reinterpret_cast<const float4*>(C + i);
        const float4 b = *reinterpret_cast<const float4*>(C + i + 4);
        f[0]=a.x; f[1]=a.y; f[2]=a.z; f[3]=a.w;
        f[4]=b.x; f[5]=b.y; f[6]=b.z; f[7]=b.w;
    }
    #pragma unroll
    for (int j = 0; j < 8; ++j) f[j] += bias[c + j];

    const int s = c >> 10;            // 0=q, 1=k, 2=v
    const int h = (c & 1023) >> 6;
    const int d = c & 63;
    const int b = t >> 11;            // /2048
    const int n = t & 2047;
    const size_t dst = (((size_t)(b * H_NUM + h)) * SEQ_N + n) * D_HEAD + d;

    if (s == 0) {
        #pragma unroll
        for (int j = 0; j < 8; ++j) f[j] *= 0.125f;
    }
    __nv_bfloat16 h8[8], l8[8];
    #pragma unroll
    for (int j = 0; j < 8; ++j) split_write(f[j], h8[j], l8[j]);

    __nv_bfloat16* ph = (s == 0) ? qhi : (s == 1) ? khi : vhi;
    __nv_bfloat16* pl = (s == 0) ? qlo : (s == 1) ? klo : vlo;
    *reinterpret_cast<uint4*>(ph + dst) = *reinterpret_cast<uint4*>(h8);
    *reinterpret_cast<uint4*>(pl + dst) = *reinterpret_cast<uint4*>(l8);
}

// ---------------------------------------------------------------------------
// Other epilogues
// ---------------------------------------------------------------------------
__global__ void epi_bias_res(const float* __restrict__ C, const float* __restrict__ bias,
                             const float* __restrict__ res, float* __restrict__ out,
                             int N, int total)
{
    const int i = (blockIdx.x * blockDim.x + threadIdx.x) * 4;
    if (i >= total) return;
    const int col = i & (N - 1);
    const float4 c = *reinterpret_cast<const float4*>(C + i);
    const float4 b = *reinterpret_cast<const float4*>(bias + col);
    const float4 r = *reinterpret_cast<const float4*>(res + i);
    float4 o = {c.x + b.x + r.x, c.y + b.y + r.y, c.z + b.z + r.z, c.w + b.w + r.w};
    *reinterpret_cast<float4*>(out + i) = o;
}

__global__ void epi_gelu_split(const float* __restrict__ C, const float* __restrict__ bias,
                               __nv_bfloat16* __restrict__ hi, __nv_bfloat16* __restrict__ lo,
                               int N, int total)
{
    const int i = (blockIdx.x * blockDim.x + threadIdx.x) * 4;
    if (i >= total) return;
    const int col = i & (N - 1);
    const float4 c = *reinterpret_cast<const float4*>(C + i);
    const float4 b = *reinterpret_cast<const float4*>(bias + col);
    float f[4] = {c.x + b.x, c.y + b.y, c.z + b.z, c.w + b.w};
    __nv_bfloat16 h4[4], l4[4];
    #pragma unroll
    for (int j = 0; j < 4; ++j) {
        const float g = 0.5f * f[j] * (1.0f + erff(f[j] * 0.70710678118654752f));
        split_write(g, h4[j], l4[j]);
    }
    *reinterpret_cast<uint2*>(hi + i) = *reinterpret_cast<uint2*>(h4);
    *reinterpret_cast<uint2*>(lo + i) = *reinterpret_cast<uint2*>(l4);
}

// ---------------------------------------------------------------------------
// Flash attention on tensor cores (wmma, bf16 hi/lo 3-term compensation).
//   grid (N/64, B*H), block 128 (4 warps). 64 q-rows per block, K-tiles of 64.
//   Dynamic smem ~109KB -> 2 blocks/SM.
//   Output written directly as hi/lo split in token-major [T,E] layout.
// ---------------------------------------------------------------------------
#define QT   64
#define KTT  64
#define LDA  72

#define SM_QHI 0
#define SM_QLO 9216
#define SM_KHI 18432
#define SM_KLO 27648
#define SM_VHI 36864
#define SM_VLO 46080
#define SM_S   55296
#define SM_PHI 73728
#define SM_PLO 82944
#define SM_O   92160
#define SM_M   110592
#define SM_L   110848
#define SM_TOT 111104

__global__ void __launch_bounds__(128)
attn_wmma(const __nv_bfloat16* __restrict__ qhi_g, const __nv_bfloat16* __restrict__ qlo_g,
          const __nv_bfloat16* __restrict__ khi_g, const __nv_bfloat16* __restrict__ klo_g,
          const __nv_bfloat16* __restrict__ vhi_g, const __nv_bfloat16* __restrict__ vlo_g,
          __nv_bfloat16* __restrict__ ohi_g, __nv_bfloat16* __restrict__ olo_g)
{
    extern __shared__ __align__(256) char smb[];
    __nv_bfloat16* Qhi = (__nv_bfloat16*)(smb + SM_QHI);
    __nv_bfloat16* Qlo = (__nv_bfloat16*)(smb + SM_QLO);
    __nv_bfloat16* Khi = (__nv_bfloat16*)(smb + SM_KHI);
    __nv_bfloat16* Klo = (__nv_bfloat16*)(smb + SM_KLO);
    __nv_bfloat16* Vhi = (__nv_bfloat16*)(smb + SM_VHI);
    __nv_bfloat16* Vlo = (__nv_bfloat16*)(smb + SM_VLO);
    float*         S   = (float*)        (smb + SM_S);
    __nv_bfloat16* Phi = (__nv_bfloat16*)(smb + SM_PHI);
    __nv_bfloat16* Plo = (__nv_bfloat16*)(smb + SM_PLO);
    float*         O   = (float*)        (smb + SM_O);
    float*         m_s = (float*)        (smb + SM_M);
    float*         l_s = (float*)        (smb + SM_L);

    const int tid = threadIdx.x;
    const int wid = tid >> 5;
    const int bh  = blockIdx.y;
    const int n0  = blockIdx.x * QT;

    // ---- load Q tile (hi/lo), zero O, init m/l
    {
        const int4* qh = (const int4*)(qhi_g + ((size_t)bh * SEQ_N + n0) * D_HEAD);
        const int4* ql = (const int4*)(qlo_g + ((size_t)bh * SEQ_N + n0) * D_HEAD);
        #pragma unroll
        for (int i = 0; i < 4; ++i) {
            const int idx = tid + i * 128;
            const int r = idx >> 3, c = (idx & 7) * 8;
            *(int4*)(Qhi + r * LDA + c) = qh[idx];
            *(int4*)(Qlo + r * LDA + c) = ql[idx];
        }
        const float4 z = {0.f, 0.f, 0.f, 0.f};
        #pragma unroll
        for (int i = 0; i < 9; ++i)
            *(float4*)(O + (tid + i * 128) * 4) = z;
        if (tid < QT) { m_s[tid] = -1e30f; l_s[tid] = 0.f; }
    }

    for (int j0 = 0; j0 < SEQ_N; j0 += KTT) {
        __syncthreads();   // prior PV consumers done before K/V overwrite
        {
            const int4* kh = (const int4*)(khi_g + ((size_t)bh * SEQ_N + j0) * D_HEAD);
            const int4* kl = (const int4*)(klo_g + ((size_t)bh * SEQ_N + j0) * D_HEAD);
            const int4* vh = (const int4*)(vhi_g + ((size_t)bh * SEQ_N + j0) * D_HEAD);
            const int4* vl = (const int4*)(vlo_g + ((size_t)bh * SEQ_N + j0) * D_HEAD);
            #pragma unroll
            for (int i = 0; i < 4; ++i) {
                const int idx = tid + i * 128;
                const int r = idx >> 3, c = (idx & 7) * 8;
                *(int4*)(Khi + r * LDA + c) = kh[idx];
                *(int4*)(Klo + r * LDA + c) = kl[idx];
                *(int4*)(Vhi + r * LDA + c) = vh[idx];
                *(int4*)(Vlo + r * LDA + c) = vl[idx];
            }
        }
        __syncthreads();

        // ---- S = Q K^T (3-term)
        {
            wmma::fragment<wmma::accumulator, 16, 16, 16, float> acc[4];
            #pragma unroll
            for (int nf = 0; nf < 4; ++nf) wmma::fill_fragment(acc[nf], 0.0f);
            #pragma unroll
            for (int ks = 0; ks < 4; ++ks) {
                wmma::fragment<wmma::matrix_a, 16, 16, 16, __nv_bfloat16, wmma::row_major> ah, al;
                wmma::load_matrix_sync(ah, Qhi + (wid * 16) * LDA + ks * 16, LDA);
                wmma::load_matrix_sync(al, Qlo + (wid * 16) * LDA + ks * 16, LDA);
                #pragma unroll
                for (int nf = 0; nf < 4; ++nf) {
                    wmma::fragment<wmma::matrix_b, 16, 16, 16, __nv_bfloat16, wmma::col_major> bh, bl;
                    wmma::load_matrix_sync(bh, Khi + (nf * 16) * LDA + ks * 16, LDA);
                    wmma::load_matrix_sync(bl, Klo + (nf * 16) * LDA + ks * 16, LDA);
                    wmma::mma_sync(acc[nf], ah, bh, acc[nf]);
                    wmma::mma_sync(acc[nf], ah, bl, acc[nf]);
                    wmma::mma_sync(acc[nf], al, bh, acc[nf]);
                }
            }
            #pragma unroll
            for (int nf = 0; nf < 4; ++nf)
                wmma::store_matrix_sync(S + (wid * 16) * LDA + nf * 16, acc[nf], LDA,
                                        wmma::mem_row_major);
        }
        __syncthreads();

        // ---- online softmax (2 threads per row), P split, O rescale
        {
            const int r  = tid >> 1;
            const int c0 = (tid & 1) * 32;
            float sv[32];
            float mloc = -1e30f;
            #pragma unroll
            for (int j = 0; j < 8; ++j) {
                const float4 s4 = *(const float4*)(S + r * LDA + c0 + j * 4);
                sv[j*4+0] = s4.x; sv[j*4+1] = s4.y; sv[j*4+2] = s4.z; sv[j*4+3] = s4.w;
                mloc = fmaxf(mloc, fmaxf(fmaxf(s4.x, s4.y), fmaxf(s4.z, s4.w)));
            }
            mloc = fmaxf(mloc, __shfl_xor_sync(0xffffffffu, mloc, 1));
            const float mo = m_s[r];
            const float mn = fmaxf(mo, mloc);
            const float alpha = __expf(mo - mn);

            float sum = 0.f;
            #pragma unroll
            for (int j = 0; j < 8; ++j) {
                float p[4];
                #pragma unroll
                for (int q = 0; q < 4; ++q) {
                    p[q] = __expf(sv[j*4+q] - mn);
                    sum += p[q];
                }
                __nv_bfloat16 h4[4], l4[4];
                #pragma unroll
                for (int q = 0; q < 4; ++q) split_write(p[q], h4[q], l4[q]);
                *(uint2*)(Phi + r * LDA + c0 + j * 4) = *(uint2*)h4;
                *(uint2*)(Plo + r * LDA + c0 + j * 4) = *(uint2*)l4;
            }
            sum += __shfl_xor_sync(0xffffffffu, sum, 1);
            if ((tid & 1) == 0) {
                m_s[r] = mn;
                l_s[r] = l_s[r] * alpha + sum;
            }
            #pragma unroll
            for (int j = 0; j < 8; ++j) {
                float4 o4 = *(float4*)(O + r * LDA + c0 + j * 4);
                o4.x *= alpha; o4.y *= alpha; o4.z *= alpha; o4.w *= alpha;
                *(float4*)(O + r * LDA + c0 + j * 4) = o4;
            }
        }
        __syncthreads();

        // ---- O += P V (3-term), accumulator loaded from rescaled O
        {
            wmma::fragment<wmma::accumulator, 16, 16, 16, float> acc[4];
            #pragma unroll
            for (int nf = 0; nf < 4; ++nf)
                wmma::load_matrix_sync(acc[nf], O + (wid * 16) * LDA + nf * 16, LDA,
                                       wmma::mem_row_major);
            #pragma unroll
            for (int ks = 0; ks < 4; ++ks) {
                wmma::fragment<wmma::matrix_a, 16, 16, 16, __nv_bfloat16, wmma::row_major> ph, pl;
                wmma::load_matrix_sync(ph, Phi + (wid * 16) * LDA + ks * 16, LDA);
                wmma::load_matrix_sync(pl, Plo + (wid * 16) * LDA + ks * 16, LDA);
                #pragma unroll
                for (int nf = 0; nf < 4; ++nf) {
                    wmma::fragment<wmma::matrix_b, 16, 16, 16, __nv_bfloat16, wmma::row_major> vh, vl;
                    wmma::load_matrix_sync(vh, Vhi + (ks * 16) * LDA + nf * 16, LDA);
                    wmma::load_matrix_sync(vl, Vlo + (ks * 16) * LDA + nf * 16, LDA);
                    wmma::mma_sync(acc[nf], ph, vh, acc[nf]);
                    wmma::mma_sync(acc[nf], ph, vl, acc[nf]);
                    wmma::mma_sync(acc[nf], pl, vh, acc[nf]);
                }
            }
            #pragma unroll
            for (int nf = 0; nf < 4; ++nf)
                wmma::store_matrix_sync(O + (wid * 16) * LDA + nf * 16, acc[nf], LDA,
                                        wmma::mem_row_major);
        }
    }
    __syncthreads();

    // ---- normalize + split-write output [token][E]
    {
        const int r  = tid >> 1;
        const int c0 = (tid & 1) * 32;
        const float inv = 1.0f / l_s[r];
        const int b = bh >> 4, h = bh & 15;
        const size_t base = ((size_t)(b * SEQ_N + n0 + r)) * E_DIM + h * D_HEAD + c0;
        #pragma unroll
        for (int j = 0; j < 8; ++j) {
            const float4 o4 = *(const float4*)(O + r * LDA + c0 + j * 4);
            const float f[4] = {o4.x * inv, o4.y * inv, o4.z * inv, o4.w * inv};
            __nv_bfloat16 h4[4], l4[4];
            #pragma unroll
            for (int q = 0; q < 4; ++q) split_write(f[q], h4[q], l4[q]);
            *(uint2*)(ohi_g + base + j * 4) = *(uint2*)h4;
            *(uint2*)(olo_g + base + j * 4) = *(uint2*)l4;
        }
    }
}

// ---------------------------------------------------------------------------
// Launch
// ---------------------------------------------------------------------------
static float* sym_addr_f(const void* symbol)
{
    void* p = nullptr;
    cudaGetSymbolAddress(&p, symbol);
    return reinterpret_cast<float*>(p);
}
static __nv_bfloat16* sym_addr_b(const void* symbol)
{
    void* p = nullptr;
    cudaGetSymbolAddress(&p, symbol);
    return reinterpret_cast<__nv_bfloat16*>(p);
}

extern "C" void kernel_launch(void* const* d_in, const int* in_sizes, int n_in,
                              void* d_out, int out_size)
{
    const float* x      = (const float*)d_in[0];
    const float* ln1_g  = (const float*)d_in[1];
    const float* ln1_b  = (const float*)d_in[2];
    const float* qkv_w  = (const float*)d_in[3];
    const float* qkv_b  = (const float*)d_in[4];
    const float* proj_w = (const float*)d_in[5];
    const float* proj_b = (const float*)d_in[6];
    const float* ln2_g  = (const float*)d_in[7];
    const float* ln2_b  = (const float*)d_in[8];
    const float* fc1_w  = (const float*)d_in[9];
    const float* fc1_b  = (const float*)d_in[10];
    const float* fc2_w  = (const float*)d_in[11];
    const float* fc2_b  = (const float*)d_in[12];
    float* out = (float*)d_out;

    __nv_bfloat16* ahi = sym_addr_b(g_ahi);
    __nv_bfloat16* alo = sym_addr_b(g_alo);
    __nv_bfloat16* whi = sym_addr_b(g_whi);
    __nv_bfloat16* wlo = sym_addr_b(g_wlo);
    float* craw = sym_addr_f(g_craw);
    float* x1   = sym_addr_f(g_x1);
    __nv_bfloat16* qhi = sym_addr_b(g_qhi);
    __nv_bfloat16* qlo = sym_addr_b(g_qlo);
    __nv_bfloat16* khi = sym_addr_b(g_khi);
    __nv_bfloat16* klo = sym_addr_b(g_klo);
    __nv_bfloat16* vhi = sym_addr_b(g_vhi);
    __nv_bfloat16* vlo = sym_addr_b(g_vlo);

    cudaFuncSetAttribute(attn_wmma, cudaFuncAttributeMaxDynamicSharedMemorySize, SM_TOT);

    const int n_qkvw  = E_DIM * 3 * E_DIM;
    const int n_projw = E_DIM * E_DIM;
    const int n_fc1w  = E_DIM * FF_DIM;
    const int n_fc2w  = FF_DIM * E_DIM;

    // 1) h = LN1(x) -> split
    ln_split_kernel<<<T_TOK, 256>>>(x, ln1_g, ln1_b, ahi, alo);

    // 2) qkv GEMM -> craw; fused epilogue: +bias, head-major hi/lo split
    split_kernel<<<n_qkvw / 1024, 256>>>(qkv_w, whi, wlo, n_qkvw);
    gemm_bf16_split<<<dim3(3 * E_DIM / 128, T_TOK / 128), 256>>>(
        ahi, alo, whi, wlo, craw, T_TOK, 3 * E_DIM, E_DIM);
    epi_qkv_split<<<(T_TOK * 3 * E_DIM) / (8 * 256), 256>>>(
        craw, qkv_b, qhi, qlo, khi, klo, vhi, vlo);

    // 3) attention (tensor cores), writes hi/lo split directly
    attn_wmma<<<dim3(SEQ_N / QT, 2 * H_NUM), 128, SM_TOT>>>(
        qhi, qlo, khi, klo, vhi, vlo, ahi, alo);

    // 4) x1 = x + attn @ proj_w + proj_b
    split_kernel<<<n_projw / 1024, 256>>>(proj_w, whi, wlo, n_projw);
    gemm_bf16_split<<<dim3(E_DIM / 128, T_TOK / 128), 256>>>(
        ahi, alo, whi, wlo, craw, T_TOK, E_DIM, E_DIM);
    epi_bias_res<<<(T_TOK * E_DIM) / 1024, 256>>>(craw, proj_b, x, x1, E_DIM, T_TOK * E_DIM);

    // 5) h = LN2(x1) -> split
    ln_split_kernel<<<T_TOK, 256>>>(x1, ln2_g, ln2_b, ahi, alo);

    // 6) ff = gelu(h @ fc1_w + fc1_b) -> split
    split_kernel<<<n_fc1w / 1024, 256>>>(fc1_w, whi, wlo, n_fc1w);
    gemm_bf16_split<<<dim3(FF_DIM / 128, T_TOK / 128), 256>>>(
        ahi, alo, whi, wlo, craw, T_TOK, FF_DIM, E_DIM);
    epi_gelu_split<<<(T_TOK * FF_DIM) / 1024, 256>>>(craw, fc1_b, ahi, alo, FF_DIM, T_TOK * FF_DIM);

    // 7) out = x1 + ff @ fc2_w + fc2_b
    split_kernel<<<n_fc2w / 1024, 256>>>(fc2_w, whi, wlo, n_fc2w);
    gemm_bf16_split<<<dim3(E_DIM / 128, T_TOK / 128), 256>>>(
        ahi, alo, whi, wlo, craw, T_TOK, E_DIM, FF_DIM);
    epi_bias_res<<<(T_TOK * E_DIM) / 1024, 256>>>(craw, fc2_b, x1, out, E_DIM, T_TOK * E_DIM);
}

// round 5
// speedup vs baseline: 4.4899x; 1.8739x over previous
#include <cuda_runtime.h>
#include <cuda_fp16.h>
#include <mma.h>
#include <math.h>
#include <cstdint>

using namespace nvcuda;

// ---------------------------------------------------------------------------
// Problem constants (B=2, N=2048, E=1024, H=16, D=64, FF=4096)
// ---------------------------------------------------------------------------
#define T_TOK   4096
#define E_DIM   1024
#define H_NUM   16
#define D_HEAD  64
#define FF_DIM  4096
#define SEQ_N   2048
#define EPS_LN  1e-5f

// ---------------------------------------------------------------------------
// Scratch (__device__ globals; allocation-free rule)
// ---------------------------------------------------------------------------
__device__ __half g_ahi[(size_t)T_TOK * E_DIM];   // activation hi (LN out / attn out)
__device__ __half g_alo[(size_t)T_TOK * E_DIM];   // activation lo
__device__ __half g_w  [(size_t)E_DIM * FF_DIM];  // weight, single fp16 (reused)
__device__ __half g_fhi[(size_t)T_TOK * FF_DIM];  // gelu(fc1) hi
__device__ __half g_flo[(size_t)T_TOK * FF_DIM];  // gelu(fc1) lo
__device__ float  g_craw[(size_t)T_TOK * FF_DIM]; // raw GEMM out
__device__ float  g_x1 [(size_t)T_TOK * E_DIM];
// attention operands, head-major [B*H][N][64]
__device__ __half g_qhi[(size_t)T_TOK * E_DIM];
__device__ __half g_qlo[(size_t)T_TOK * E_DIM];
__device__ __half g_k  [(size_t)T_TOK * E_DIM];
__device__ __half g_v  [(size_t)T_TOK * E_DIM];

// ---------------------------------------------------------------------------
// Helpers
// ---------------------------------------------------------------------------
__device__ __forceinline__ float warp_sum(float v) {
    #pragma unroll
    for (int o = 16; o > 0; o >>= 1) v += __shfl_xor_sync(0xffffffffu, v, o);
    return v;
}
__device__ __forceinline__ void split_write(float f, __half& hi, __half& lo) {
    __half h = __float2half_rn(f);
    hi = h;
    lo = __float2half_rn(f - __half2float(h));
}

// ---------------------------------------------------------------------------
// LayerNorm -> fp16 hi/lo split
// ---------------------------------------------------------------------------
__global__ void ln_split_kernel(const float* __restrict__ x,
                                const float* __restrict__ gamma,
                                const float* __restrict__ beta,
                                __half* __restrict__ ohi,
                                __half* __restrict__ olo)
{
    const int row = blockIdx.x;
    const int tid = threadIdx.x;
    const int w   = tid >> 5;
    const int ln  = tid & 31;

    const float4 v = reinterpret_cast<const float4*>(x + (size_t)row * E_DIM)[tid];
    float s  = v.x + v.y + v.z + v.w;
    float sq = v.x * v.x + v.y * v.y + v.z * v.z + v.w * v.w;
    s  = warp_sum(s);
    sq = warp_sum(sq);

    __shared__ float red_s[8], red_q[8];
    __shared__ float s_mu, s_rs;
    if (ln == 0) { red_s[w] = s; red_q[w] = sq; }
    __syncthreads();
    if (w == 0) {
        float ts = (ln < 8) ? red_s[ln] : 0.f;
        float tq = (ln < 8) ? red_q[ln] : 0.f;
        ts = warp_sum(ts); tq = warp_sum(tq);
        if (ln == 0) {
            float mu  = ts * (1.0f / E_DIM);
            float var = tq * (1.0f / E_DIM) - mu * mu;
            s_mu = mu; s_rs = rsqrtf(var + EPS_LN);
        }
    }
    __syncthreads();
    const float mu = s_mu, rs = s_rs;

    const float4 g = reinterpret_cast<const float4*>(gamma)[tid];
    const float4 b = reinterpret_cast<const float4*>(beta)[tid];
    float o[4];
    o[0] = (v.x - mu) * rs * g.x + b.x;
    o[1] = (v.y - mu) * rs * g.y + b.y;
    o[2] = (v.z - mu) * rs * g.z + b.z;
    o[3] = (v.w - mu) * rs * g.w + b.w;

    __half h4[4], l4[4];
    #pragma unroll
    for (int j = 0; j < 4; ++j) split_write(o[j], h4[j], l4[j]);
    const size_t off = (size_t)row * E_DIM + tid * 4;
    *reinterpret_cast<uint2*>(ohi + off) = *reinterpret_cast<uint2*>(h4);
    *reinterpret_cast<uint2*>(olo + off) = *reinterpret_cast<uint2*>(l4);
}

// ---------------------------------------------------------------------------
// fp32 -> fp16 (weights, single rounding)
// ---------------------------------------------------------------------------
__global__ void wconv_kernel(const float* __restrict__ src,
                             __half* __restrict__ dst, int n)
{
    const int i = (blockIdx.x * blockDim.x + threadIdx.x) * 4;
    if (i >= n) return;
    const float4 v = *reinterpret_cast<const float4*>(src + i);
    __half h4[4];
    h4[0] = __float2half_rn(v.x); h4[1] = __float2half_rn(v.y);
    h4[2] = __float2half_rn(v.z); h4[3] = __float2half_rn(v.w);
    *reinterpret_cast<uint2*>(dst + i) = *reinterpret_cast<uint2*>(h4);
}

// ---------------------------------------------------------------------------
// fp16 2-term split GEMM (wmma m16n16k16): C = (Ah+Al)[M,K] @ B[K,N]
//   128x128 block, 8 warps (warp tile 64x32), k-tile 32, reg-prefetch.
// ---------------------------------------------------------------------------
__global__ void __launch_bounds__(256)
gemm_fp16_2t(const __half* __restrict__ Ahi, const __half* __restrict__ Alo,
             const __half* __restrict__ B, float* __restrict__ C,
             int M, int N, int K)
{
    __shared__ __half As[2][128][40];   // [hi/lo][row][k]
    __shared__ __half Bs[32][136];      // [k][n]

    const int tid = threadIdx.x;
    const int wid = tid >> 5;
    const int wm  = wid & 1;
    const int wn  = wid >> 1;
    const int m0  = blockIdx.y * 128;
    const int n0  = blockIdx.x * 128;

    wmma::fragment<wmma::accumulator, 16, 16, 16, float> acc[4][2];
    #pragma unroll
    for (int i = 0; i < 4; ++i)
        #pragma unroll
        for (int j = 0; j < 2; ++j) wmma::fill_fragment(acc[i][j], 0.0f);

    int4 pa[2][2], pb[2];

    #pragma unroll
    for (int h = 0; h < 2; ++h) {
        const __half* Asrc = h ? Alo : Ahi;
        #pragma unroll
        for (int r = 0; r < 2; ++r) {
            const int ca = tid * 2 + r;
            pa[h][r] = *reinterpret_cast<const int4*>(
                Asrc + (size_t)(m0 + (ca >> 2)) * K + (ca & 3) * 8);
        }
    }
    #pragma unroll
    for (int r = 0; r < 2; ++r) {
        const int ca = tid * 2 + r;
        pb[r] = *reinterpret_cast<const int4*>(
            B + (size_t)(ca >> 4) * N + n0 + (ca & 15) * 8);
    }

    for (int k0 = 0; k0 < K; k0 += 32) {
        #pragma unroll
        for (int h = 0; h < 2; ++h)
            #pragma unroll
            for (int r = 0; r < 2; ++r) {
                const int ca = tid * 2 + r;
                *reinterpret_cast<int4*>(&As[h][ca >> 2][(ca & 3) * 8]) = pa[h][r];
            }
        #pragma unroll
        for (int r = 0; r < 2; ++r) {
            const int ca = tid * 2 + r;
            *reinterpret_cast<int4*>(&Bs[ca >> 4][(ca & 15) * 8]) = pb[r];
        }
        __syncthreads();

        if (k0 + 32 < K) {
            #pragma unroll
            for (int h = 0; h < 2; ++h) {
                const __half* Asrc = h ? Alo : Ahi;
                #pragma unroll
                for (int r = 0; r < 2; ++r) {
                    const int ca = tid * 2 + r;
                    pa[h][r] = *reinterpret_cast<const int4*>(
                        Asrc + (size_t)(m0 + (ca >> 2)) * K + k0 + 32 + (ca & 3) * 8);
                }
            }
            #pragma unroll
            for (int r = 0; r < 2; ++r) {
                const int ca = tid * 2 + r;
                pb[r] = *reinterpret_cast<const int4*>(
                    B + (size_t)(k0 + 32 + (ca >> 4)) * N + n0 + (ca & 15) * 8);
            }
        }

        #pragma unroll
        for (int kk = 0; kk < 2; ++kk) {
            wmma::fragment<wmma::matrix_a, 16, 16, 16, __half, wmma::row_major> ah[4], al[4];
            wmma::fragment<wmma::matrix_b, 16, 16, 16, __half, wmma::row_major> bf[2];
            #pragma unroll
            for (int i = 0; i < 4; ++i) {
                wmma::load_matrix_sync(ah[i], &As[0][wm * 64 + i * 16][kk * 16], 40);
                wmma::load_matrix_sync(al[i], &As[1][wm * 64 + i * 16][kk * 16], 40);
            }
            #pragma unroll
            for (int j = 0; j < 2; ++j)
                wmma::load_matrix_sync(bf[j], &Bs[kk * 16][wn * 32 + j * 16], 136);
            #pragma unroll
            for (int i = 0; i < 4; ++i)
                #pragma unroll
                for (int j = 0; j < 2; ++j) {
                    wmma::mma_sync(acc[i][j], ah[i], bf[j], acc[i][j]);
                    wmma::mma_sync(acc[i][j], al[i], bf[j], acc[i][j]);
                }
        }
        __syncthreads();
    }

    #pragma unroll
    for (int i = 0; i < 4; ++i)
        #pragma unroll
        for (int j = 0; j < 2; ++j)
            wmma::store_matrix_sync(&C[(size_t)(m0 + wm * 64 + i * 16) * N + n0 + wn * 32 + j * 16],
                                    acc[i][j], N, wmma::mem_row_major);
}

// ---------------------------------------------------------------------------
// QKV epilogue: craw + bias -> head-major q(hi/lo, *0.125), k, v (fp16)
// ---------------------------------------------------------------------------
__global__ void epi_qkv_split(const float* __restrict__ C, const float* __restrict__ bias,
                              __half* __restrict__ qhi, __half* __restrict__ qlo,
                              __half* __restrict__ kk_, __half* __restrict__ vv_)
{
    const size_t i = ((size_t)blockIdx.x * blockDim.x + threadIdx.x) * 8;
    const int t = (int)(i / (3 * E_DIM));
    const int c = (int)(i % (3 * E_DIM));

    float f[8];
    {
        const float4 a = *reinterpret_cast<const float4*>(C + i);
        const float4 b = *reinterpret_cast<const float4*>(C + i + 4);
        f[0]=a.x; f[1]=a.y; f[2]=a.z; f[3]=a.w;
        f[4]=b.x; f[5]=b.y; f[6]=b.z; f[7]=b.w;
    }
    #pragma unroll
    for (int j = 0; j < 8; ++j) f[j] += bias[c + j];

    const int s = c >> 10;            // 0=q, 1=k, 2=v
    const int h = (c & 1023) >> 6;
    const int d = c & 63;
    const int b = t >> 11;
    const int n = t & 2047;
    const size_t dst = (((size_t)(b * H_NUM + h)) * SEQ_N + n) * D_HEAD + d;

    if (s == 0) {
        __half h8[8], l8[8];
        #pragma unroll
        for (int j = 0; j < 8; ++j) split_write(f[j] * 0.125f, h8[j], l8[j]);
        *reinterpret_cast<uint4*>(qhi + dst) = *reinterpret_cast<uint4*>(h8);
        *reinterpret_cast<uint4*>(qlo + dst) = *reinterpret_cast<uint4*>(l8);
    } else {
        __half h8[8];
        #pragma unroll
        for (int j = 0; j < 8; ++j) h8[j] = __float2half_rn(f[j]);
        __half* p = (s == 1) ? kk_ : vv_;
        *reinterpret_cast<uint4*>(p + dst) = *reinterpret_cast<uint4*>(h8);
    }
}

// ---------------------------------------------------------------------------
// Other epilogues
// ---------------------------------------------------------------------------
__global__ void epi_bias_res(const float* __restrict__ C, const float* __restrict__ bias,
                             const float* __restrict__ res, float* __restrict__ out,
                             int N, int total)
{
    const int i = (blockIdx.x * blockDim.x + threadIdx.x) * 4;
    if (i >= total) return;
    const int col = i & (N - 1);
    const float4 c = *reinterpret_cast<const float4*>(C + i);
    const float4 b = *reinterpret_cast<const float4*>(bias + col);
    const float4 r = *reinterpret_cast<const float4*>(res + i);
    float4 o = {c.x + b.x + r.x, c.y + b.y + r.y, c.z + b.z + r.z, c.w + b.w + r.w};
    *reinterpret_cast<float4*>(out + i) = o;
}

__global__ void epi_gelu_split(const float* __restrict__ C, const float* __restrict__ bias,
                               __half* __restrict__ hi, __half* __restrict__ lo,
                               int N, int total)
{
    const int i = (blockIdx.x * blockDim.x + threadIdx.x) * 4;
    if (i >= total) return;
    const int col = i & (N - 1);
    const float4 c = *reinterpret_cast<const float4*>(C + i);
    const float4 b = *reinterpret_cast<const float4*>(bias + col);
    float f[4] = {c.x + b.x, c.y + b.y, c.z + b.z, c.w + b.w};
    __half h4[4], l4[4];
    #pragma unroll
    for (int j = 0; j < 4; ++j) {
        const float g = 0.5f * f[j] * (1.0f + erff(f[j] * 0.70710678118654752f));
        split_write(g, h4[j], l4[j]);
    }
    *reinterpret_cast<uint2*>(hi + i) = *reinterpret_cast<uint2*>(h4);
    *reinterpret_cast<uint2*>(lo + i) = *reinterpret_cast<uint2*>(l4);
}

// ---------------------------------------------------------------------------
// Flash attention (wmma fp16, 2-term: Q split, K/V single).
//   grid (N/64, B*H), block 128 (4 warps). smem ~90.5KB -> 2 CTAs/SM.
// ---------------------------------------------------------------------------
#define QT   64
#define KTT  64
#define LDA  72

#define SM_QHI 0
#define SM_QLO 9216
#define SM_K   18432
#define SM_V   27648
#define SM_S   36864
#define SM_PHI 55296
#define SM_PLO 64512
#define SM_O   73728
#define SM_M   92160
#define SM_L   92416
#define SM_TOT 92672

__global__ void __launch_bounds__(128)
attn_wmma(const __half* __restrict__ qhi_g, const __half* __restrict__ qlo_g,
          const __half* __restrict__ k_g, const __half* __restrict__ v_g,
          __half* __restrict__ ohi_g, __half* __restrict__ olo_g)
{
    extern __shared__ __align__(256) char smb[];
    __half* Qhi = (__half*)(smb + SM_QHI);
    __half* Qlo = (__half*)(smb + SM_QLO);
    __half* Ks  = (__half*)(smb + SM_K);
    __half* Vs  = (__half*)(smb + SM_V);
    float*  S   = (float*) (smb + SM_S);
    __half* Phi = (__half*)(smb + SM_PHI);
    __half* Plo = (__half*)(smb + SM_PLO);
    float*  O   = (float*) (smb + SM_O);
    float*  m_s = (float*) (smb + SM_M);
    float*  l_s = (float*) (smb + SM_L);

    const int tid = threadIdx.x;
    const int wid = tid >> 5;
    const int bh  = blockIdx.y;
    const int n0  = blockIdx.x * QT;

    {
        const int4* qh = (const int4*)(qhi_g + ((size_t)bh * SEQ_N + n0) * D_HEAD);
        const int4* ql = (const int4*)(qlo_g + ((size_t)bh * SEQ_N + n0) * D_HEAD);
        #pragma unroll
        for (int i = 0; i < 4; ++i) {
            const int idx = tid + i * 128;
            const int r = idx >> 3, c = (idx & 7) * 8;
            *(int4*)(Qhi + r * LDA + c) = qh[idx];
            *(int4*)(Qlo + r * LDA + c) = ql[idx];
        }
        const float4 z = {0.f, 0.f, 0.f, 0.f};
        #pragma unroll
        for (int i = 0; i < 9; ++i)
            *(float4*)(O + (tid + i * 128) * 4) = z;
        if (tid < QT) { m_s[tid] = -1e30f; l_s[tid] = 0.f; }
    }

    for (int j0 = 0; j0 < SEQ_N; j0 += KTT) {
        __syncthreads();
        {
            const int4* kh = (const int4*)(k_g + ((size_t)bh * SEQ_N + j0) * D_HEAD);
            const int4* vh = (const int4*)(v_g + ((size_t)bh * SEQ_N + j0) * D_HEAD);
            #pragma unroll
            for (int i = 0; i < 4; ++i) {
                const int idx = tid + i * 128;
                const int r = idx >> 3, c = (idx & 7) * 8;
                *(int4*)(Ks + r * LDA + c) = kh[idx];
                *(int4*)(Vs + r * LDA + c) = vh[idx];
            }
        }
        __syncthreads();

        // ---- S = Q K^T (2-term)
        {
            wmma::fragment<wmma::accumulator, 16, 16, 16, float> acc[4];
            #pragma unroll
            for (int nf = 0; nf < 4; ++nf) wmma::fill_fragment(acc[nf], 0.0f);
            #pragma unroll
            for (int ks = 0; ks < 4; ++ks) {
                wmma::fragment<wmma::matrix_a, 16, 16, 16, __half, wmma::row_major> ah, al;
                wmma::load_matrix_sync(ah, Qhi + (wid * 16) * LDA + ks * 16, LDA);
                wmma::load_matrix_sync(al, Qlo + (wid * 16) * LDA + ks * 16, LDA);
                #pragma unroll
                for (int nf = 0; nf < 4; ++nf) {
                    wmma::fragment<wmma::matrix_b, 16, 16, 16, __half, wmma::col_major> bf;
                    wmma::load_matrix_sync(bf, Ks + (nf * 16) * LDA + ks * 16, LDA);
                    wmma::mma_sync(acc[nf], ah, bf, acc[nf]);
                    wmma::mma_sync(acc[nf], al, bf, acc[nf]);
                }
            }
            #pragma unroll
            for (int nf = 0; nf < 4; ++nf)
                wmma::store_matrix_sync(S + (wid * 16) * LDA + nf * 16, acc[nf], LDA,
                                        wmma::mem_row_major);
        }
        __syncthreads();

        // ---- online softmax (2 threads/row), P split fp16, O rescale
        {
            const int r  = tid >> 1;
            const int c0 = (tid & 1) * 32;
            float sv[32];
            float mloc = -1e30f;
            #pragma unroll
            for (int j = 0; j < 8; ++j) {
                const float4 s4 = *(const float4*)(S + r * LDA + c0 + j * 4);
                sv[j*4+0] = s4.x; sv[j*4+1] = s4.y; sv[j*4+2] = s4.z; sv[j*4+3] = s4.w;
                mloc = fmaxf(mloc, fmaxf(fmaxf(s4.x, s4.y), fmaxf(s4.z, s4.w)));
            }
            mloc = fmaxf(mloc, __shfl_xor_sync(0xffffffffu, mloc, 1));
            const float mo = m_s[r];
            const float mn = fmaxf(mo, mloc);
            const float alpha = __expf(mo - mn);

            float sum = 0.f;
            #pragma unroll
            for (int j = 0; j < 8; ++j) {
                float p[4];
                #pragma unroll
                for (int q = 0; q < 4; ++q) {
                    p[q] = __expf(sv[j*4+q] - mn);
                    sum += p[q];
                }
                __half h4[4], l4[4];
                #pragma unroll
                for (int q = 0; q < 4; ++q) split_write(p[q], h4[q], l4[q]);
                *(uint2*)(Phi + r * LDA + c0 + j * 4) = *(uint2*)h4;
                *(uint2*)(Plo + r * LDA + c0 + j * 4) = *(uint2*)l4;
            }
            sum += __shfl_xor_sync(0xffffffffu, sum, 1);
            if ((tid & 1) == 0) {
                m_s[r] = mn;
                l_s[r] = l_s[r] * alpha + sum;
            }
            #pragma unroll
            for (int j = 0; j < 8; ++j) {
                float4 o4 = *(float4*)(O + r * LDA + c0 + j * 4);
                o4.x *= alpha; o4.y *= alpha; o4.z *= alpha; o4.w *= alpha;
                *(float4*)(O + r * LDA + c0 + j * 4) = o4;
            }
        }
        __syncthreads();

        // ---- O += P V (2-term: P split, V single)
        {
            wmma::fragment<wmma::accumulator, 16, 16, 16, float> acc[4];
            #pragma unroll
            for (int nf = 0; nf < 4; ++nf)
                wmma::load_matrix_sync(acc[nf], O + (wid * 16) * LDA + nf * 16, LDA,
                                       wmma::mem_row_major);
            #pragma unroll
            for (int ks = 0; ks < 4; ++ks) {
                wmma::fragment<wmma::matrix_a, 16, 16, 16, __half, wmma::row_major> ph, pl;
                wmma::load_matrix_sync(ph, Phi + (wid * 16) * LDA + ks * 16, LDA);
                wmma::load_matrix_sync(pl, Plo + (wid * 16) * LDA + ks * 16, LDA);
                #pragma unroll
                for (int nf = 0; nf < 4; ++nf) {
                    wmma::fragment<wmma::matrix_b, 16, 16, 16, __half, wmma::row_major> vf;
                    wmma::load_matrix_sync(vf, Vs + (ks * 16) * LDA + nf * 16, LDA);
                    wmma::mma_sync(acc[nf], ph, vf, acc[nf]);
                    wmma::mma_sync(acc[nf], pl, vf, acc[nf]);
                }
            }
            #pragma unroll
            for (int nf = 0; nf < 4; ++nf)
                wmma::store_matrix_sync(O + (wid * 16) * LDA + nf * 16, acc[nf], LDA,
                                        wmma::mem_row_major);
        }
    }
    __syncthreads();

    // ---- normalize + split-write output [token][E]
    {
        const int r  = tid >> 1;
        const int c0 = (tid & 1) * 32;
        const float inv = 1.0f / l_s[r];
        const int b = bh >> 4, h = bh & 15;
        const size_t base = ((size_t)(b * SEQ_N + n0 + r)) * E_DIM + h * D_HEAD + c0;
        #pragma unroll
        for (int j = 0; j < 8; ++j) {
            const float4 o4 = *(const float4*)(O + r * LDA + c0 + j * 4);
            const float f[4] = {o4.x * inv, o4.y * inv, o4.z * inv, o4.w * inv};
            __half h4[4], l4[4];
            #pragma unroll
            for (int q = 0; q < 4; ++q) split_write(f[q], h4[q], l4[q]);
            *(uint2*)(ohi_g + base + j * 4) = *(uint2*)h4;
            *(uint2*)(olo_g + base + j * 4) = *(uint2*)l4;
        }
    }
}

// ---------------------------------------------------------------------------
// Launch
// ---------------------------------------------------------------------------
static float* sym_addr_f(const void* symbol)
{
    void* p = nullptr;
    cudaGetSymbolAddress(&p, symbol);
    return reinterpret_cast<float*>(p);
}
static __half* sym_addr_h(const void* symbol)
{
    void* p = nullptr;
    cudaGetSymbolAddress(&p, symbol);
    return reinterpret_cast<__half*>(p);
}

extern "C" void kernel_launch(void* const* d_in, const int* in_sizes, int n_in,
                              void* d_out, int out_size)
{
    const float* x      = (const float*)d_in[0];
    const float* ln1_g  = (const float*)d_in[1];
    const float* ln1_b  = (const float*)d_in[2];
    const float* qkv_w  = (const float*)d_in[3];
    const float* qkv_b  = (const float*)d_in[4];
    const float* proj_w = (const float*)d_in[5];
    const float* proj_b = (const float*)d_in[6];
    const float* ln2_g  = (const float*)d_in[7];
    const float* ln2_b  = (const float*)d_in[8];
    const float* fc1_w  = (const float*)d_in[9];
    const float* fc1_b  = (const float*)d_in[10];
    const float* fc2_w  = (const float*)d_in[11];
    const float* fc2_b  = (const float*)d_in[12];
    float* out = (float*)d_out;

    __half* ahi = sym_addr_h(g_ahi);
    __half* alo = sym_addr_h(g_alo);
    __half* w   = sym_addr_h(g_w);
    __half* fhi = sym_addr_h(g_fhi);
    __half* flo = sym_addr_h(g_flo);
    float* craw = sym_addr_f(g_craw);
    float* x1   = sym_addr_f(g_x1);
    __half* qhi = sym_addr_h(g_qhi);
    __half* qlo = sym_addr_h(g_qlo);
    __half* kk  = sym_addr_h(g_k);
    __half* vv  = sym_addr_h(g_v);

    cudaFuncSetAttribute(attn_wmma, cudaFuncAttributeMaxDynamicSharedMemorySize, SM_TOT);

    const int n_qkvw  = E_DIM * 3 * E_DIM;
    const int n_projw = E_DIM * E_DIM;
    const int n_fc1w  = E_DIM * FF_DIM;
    const int n_fc2w  = FF_DIM * E_DIM;

    // 1) h = LN1(x) -> fp16 hi/lo
    ln_split_kernel<<<T_TOK, 256>>>(x, ln1_g, ln1_b, ahi, alo);

    // 2) qkv = h @ qkv_w + qkv_b  -> head-major q(hi/lo)/k/v
    wconv_kernel<<<n_qkvw / 1024, 256>>>(qkv_w, w, n_qkvw);
    gemm_fp16_2t<<<dim3(3 * E_DIM / 128, T_TOK / 128), 256>>>(
        ahi, alo, w, craw, T_TOK, 3 * E_DIM, E_DIM);
    epi_qkv_split<<<(T_TOK * 3 * E_DIM) / (8 * 256), 256>>>(
        craw, qkv_b, qhi, qlo, kk, vv);

    // 3) attention -> fp16 hi/lo (token-major)
    attn_wmma<<<dim3(SEQ_N / QT, 2 * H_NUM), 128, SM_TOT>>>(
        qhi, qlo, kk, vv, ahi, alo);

    // 4) x1 = x + attn @ proj_w + proj_b
    wconv_kernel<<<n_projw / 1024, 256>>>(proj_w, w, n_projw);
    gemm_fp16_2t<<<dim3(E_DIM / 128, T_TOK / 128), 256>>>(
        ahi, alo, w, craw, T_TOK, E_DIM, E_DIM);
    epi_bias_res<<<(T_TOK * E_DIM) / 1024, 256>>>(craw, proj_b, x, x1, E_DIM, T_TOK * E_DIM);

    // 5) h = LN2(x1) -> fp16 hi/lo
    ln_split_kernel<<<T_TOK, 256>>>(x1, ln2_g, ln2_b, ahi, alo);

    // 6) ff = gelu(h @ fc1_w + fc1_b) -> fp16 hi/lo
    wconv_kernel<<<n_fc1w / 1024, 256>>>(fc1_w, w, n_fc1w);
    gemm_fp16_2t<<<dim3(FF_DIM / 128, T_TOK / 128), 256>>>(
        ahi, alo, w, craw, T_TOK, FF_DIM, E_DIM);
    epi_gelu_split<<<(T_TOK * FF_DIM) / 1024, 256>>>(craw, fc1_b, fhi, flo, FF_DIM, T_TOK * FF_DIM);

    // 7) out = x1 + ff @ fc2_w + fc2_b
    wconv_kernel<<<n_fc2w / 1024, 256>>>(fc2_w, w, n_fc2w);
    gemm_fp16_2t<<<dim3(E_DIM / 128, T_TOK / 128), 256>>>(
        fhi, flo, w, craw, T_TOK, E_DIM, FF_DIM);
    epi_bias_res<<<(T_TOK * E_DIM) / 1024, 256>>>(craw, fc2_b, x1, out, E_DIM, T_TOK * E_DIM);
}